// round 4
// baseline (speedup 1.0000x reference)
#include <cuda_runtime.h>
#include <cuda_bf16.h>

// Sliding-window unfold: out[b, i, j] = x[b, i + j]
//   x:   [B=128, L=8192]  float32
//   out: [B=128, NWIN=8162, W=31] float32
//
// R4: aligned LDS.128 via 4 alignment-replicated smem copies.
// Each thread's 4 outputs draw from two contiguous source runs:
//   run A: s..s+3        (non-wrapped lanes k < m, m = 31-j)
//   run B: (s-30)..(s-27) (wrapped lanes, element k = (s-30)+k)
// copy_r[idx] = x[i0 + idx - 32 - r]  ->  quad at base p is one aligned
// LDS.128 from copy[(4-(p&3))&3]. Hot path: 2x LDS.128 + selects + STG.128.

static constexpr unsigned Bv    = 128u;
static constexpr unsigned Lv    = 8192u;
static constexpr unsigned Wv    = 31u;
static constexpr unsigned Rv    = Wv / 2u;           // 15
static constexpr unsigned NWIN  = Lv - 2u * Rv;      // 8162
static constexpr unsigned ROW   = NWIN * Wv;         // 253022
static constexpr unsigned TOTAL = Bv * ROW;          // 32,386,816
static constexpr unsigned OUTS_PER_BLOCK = 1024u;    // 256 thr x 4
static constexpr unsigned NBLOCKS = (TOTAL + OUTS_PER_BLOCK - 1u) / OUTS_PER_BLOCK; // 31628

static constexpr unsigned CPY_W = 116u;              // floats per copy (padded, 29 granules)
static constexpr unsigned CPY_N = 4u * CPY_W;        // 464

__global__ void __launch_bounds__(256)
WindowAlignmentLayer_65876208386448_kernel(const float* __restrict__ x,
                                           float* __restrict__ out) {
    __shared__ __align__(16) float s4[4][CPY_W];

    const unsigned t  = threadIdx.x;
    const unsigned o0 = blockIdx.x * OUTS_PER_BLOCK;   // block's first flat output

    const unsigned b0   = o0 / ROW;                    // magic-multiply
    const unsigned rem0 = o0 - b0 * ROW;

    const bool fast = (rem0 + OUTS_PER_BLOCK <= ROW) && (o0 + OUTS_PER_BLOCK <= TOTAL);

    if (__builtin_expect(fast, 1)) {
        const unsigned i0 = rem0 / Wv;
        const float* __restrict__ xrow = x + (size_t)b0 * Lv;

        // Stage 4 alignment-shifted copies: copy_r[idx] = x[i0 + idx - 32 - r]
        // (clamped; clamped entries are never selected by any lane).
#pragma unroll
        for (unsigned c = t; c < CPY_N; c += 256u) {
            unsigned r   = c / CPY_W;                  // const divisor
            unsigned idx = c - r * CPY_W;
            int q = (int)idx - 32 - (int)r;
            int g = (int)i0 + q;
            g = g < 0 ? 0 : (g > (int)(Lv - 1u) ? (int)(Lv - 1u) : g);
            s4[r][idx] = xrow[g];
        }
        __syncthreads();

        const unsigned rem = rem0 + t * 4u;
        const unsigned i   = rem / Wv;                 // magic-multiply
        const unsigned j   = rem - i * Wv;
        const unsigned s   = i - i0 + j;               // local base of run A
        const unsigned m   = Wv - j;                   // lanes k<m are non-wrapped (m>=1)

        // Quad A: elements s..s+3 -> copy rA at idx ua+rA (aligned).
        const unsigned ua  = s + 32u;
        const unsigned rA  = (4u - (ua & 3u)) & 3u;
        const float4 qa = *reinterpret_cast<const float4*>(&s4[rA][ua + rA]);

        // Quad B: elements (s-30)..(s-27); wrapped lane k reads element (s-30)+k.
        const unsigned ub  = s + 2u;                   // (s-30) + 32
        const unsigned rB  = (4u - (ub & 3u)) & 3u;
        const float4 qb = *reinterpret_cast<const float4*>(&s4[rB][ub + rB]);

        float4 o4;
        o4.x = qa.x;                                   // k=0 never wraps
        o4.y = (1u < m) ? qa.y : qb.y;
        o4.z = (2u < m) ? qa.z : qb.z;
        o4.w = (3u < m) ? qa.w : qb.w;

        *reinterpret_cast<float4*>(out + (o0 + t * 4u)) = o4;
        return;
    }

    // ---- Cold path: block straddles a batch row, or is the partial tail. ----
    const unsigned o = o0 + t * 4u;
    if (o >= TOTAL) return;

    const unsigned b   = o / ROW;
    const unsigned rem = o - b * ROW;
    const unsigned i   = rem / Wv;
    const unsigned j   = rem - i * Wv;
    const float* __restrict__ xrow = x + (size_t)b * Lv;

    float v[4];
#pragma unroll
    for (int k = 0; k < 4; ++k) {
        unsigned rk = rem + (unsigned)k;
        const float* __restrict__ xr = xrow;
        unsigned src;
        if (rk >= ROW) {                               // spills into next batch
            xr  = xrow + Lv;
            src = rk - ROW;                            // < 4 -> i'=0, j'=src
        } else {
            unsigned jk = j + (unsigned)k;
            src = i + jk - (jk >= Wv ? (Wv - 1u) : 0u);
        }
        v[k] = __ldg(xr + src);
    }
    float4 o4;
    o4.x = v[0]; o4.y = v[1]; o4.z = v[2]; o4.w = v[3];
    *reinterpret_cast<float4*>(out + o) = o4;
}

extern "C" void kernel_launch(void* const* d_in, const int* in_sizes, int n_in,
                              void* d_out, int out_size) {
    (void)in_sizes; (void)n_in; (void)out_size;
    const float* x   = (const float*)d_in[0];
    float*       out = (float*)d_out;

    WindowAlignmentLayer_65876208386448_kernel<<<NBLOCKS, 256>>>(x, out);
}

// round 5
// speedup vs baseline: 1.0120x; 1.0120x over previous
#include <cuda_runtime.h>
#include <cuda_bf16.h>

// Sliding-window unfold: out[b, i, j] = x[b, i + j]
//   x:   [B=128, L=8192]  float32
//   out: [B=128, NWIN=8162, W=31] float32
//
// R5: skewed-smem scalar LDS (conflict-free, 1 wavefront per LDS) +
// 8 outputs/thread (2x STG.128). Block = 2048 consecutive flat outputs;
// source span <= 97 floats staged once (phys(idx) = idx + idx/32 skew).

static constexpr unsigned Bv    = 128u;
static constexpr unsigned Lv    = 8192u;
static constexpr unsigned Wv    = 31u;
static constexpr unsigned Rv    = Wv / 2u;           // 15
static constexpr unsigned NWIN  = Lv - 2u * Rv;      // 8162
static constexpr unsigned ROW   = NWIN * Wv;         // 253022
static constexpr unsigned TOTAL = Bv * ROW;          // 32,386,816
static constexpr unsigned OPT   = 8u;                // outputs per thread
static constexpr unsigned OUTS_PER_BLOCK = 256u * OPT;               // 2048
static constexpr unsigned NBLOCKS = (TOTAL + OUTS_PER_BLOCK - 1u) / OUTS_PER_BLOCK; // 15814

static constexpr unsigned SPAN  = 104u;              // staged floats (src max 96 + pad)
static constexpr unsigned SPHYS = SPAN + SPAN / 32u; // 107 (skewed extent)

__global__ void __launch_bounds__(256)
WindowAlignmentLayer_65876208386448_kernel(const float* __restrict__ x,
                                           float* __restrict__ out) {
    __shared__ float sx[SPHYS + 1u];

    const unsigned t  = threadIdx.x;
    const unsigned o0 = blockIdx.x * OUTS_PER_BLOCK;

    const unsigned b0   = o0 / ROW;                    // magic-multiply
    const unsigned rem0 = o0 - b0 * ROW;

    const bool fast = (rem0 + OUTS_PER_BLOCK <= ROW) && (o0 + OUTS_PER_BLOCK <= TOTAL);

    if (__builtin_expect(fast, 1)) {
        const unsigned i0 = rem0 / Wv;
        const float* __restrict__ xrow = x + (size_t)b0 * Lv;

        // Stage sources [i0, i0+SPAN) into skewed smem: phys(t) = t + t/32.
        // (Clamp pads only; every selected src has global index <= L-1.)
        if (t < SPAN) {
            unsigned g = i0 + t;
            sx[t + (t >> 5)] = xrow[g < Lv ? g : (Lv - 1u)];
        }
        __syncthreads();

        const unsigned rem = rem0 + t * OPT;
        const unsigned i   = rem / Wv;                 // magic-multiply
        const unsigned j   = rem - i * Wv;
        const unsigned sA  = i - i0 + j;               // local src base (run A)
        const unsigned m   = Wv - j;                   // k >= m -> wrapped (run B)

        float v[OPT];
#pragma unroll
        for (unsigned k = 0; k < OPT; ++k) {
            // run A: src = sA+k ; run B (window wrap): src = sA+k-30
            unsigned src = sA + k - ((k >= m) ? (Wv - 1u) : 0u);
            v[k] = sx[src + (src >> 5)];
        }

        float4 q0, q1;
        q0.x = v[0]; q0.y = v[1]; q0.z = v[2]; q0.w = v[3];
        q1.x = v[4]; q1.y = v[5]; q1.z = v[6]; q1.w = v[7];
        float4* __restrict__ op = reinterpret_cast<float4*>(out + (o0 + t * OPT));
        op[0] = q0;
        op[1] = q1;
        return;
    }

    // ---- Cold path: straddles a batch row, or partial tail (~128 blocks). ----
#pragma unroll
    for (unsigned k = 0; k < OPT; ++k) {
        unsigned o = o0 + t * OPT + k;
        if (o >= TOTAL) return;
        unsigned b   = o / ROW;
        unsigned rem = o - b * ROW;
        unsigned i   = rem / Wv;
        unsigned j   = rem - i * Wv;
        out[o] = __ldg(x + (size_t)b * Lv + (i + j));
    }
}

extern "C" void kernel_launch(void* const* d_in, const int* in_sizes, int n_in,
                              void* d_out, int out_size) {
    (void)in_sizes; (void)n_in; (void)out_size;
    const float* x   = (const float*)d_in[0];
    float*       out = (float*)d_out;

    WindowAlignmentLayer_65876208386448_kernel<<<NBLOCKS, 256>>>(x, out);
}

// round 7
// speedup vs baseline: 1.4009x; 1.3843x over previous
#include <cuda_runtime.h>
#include <cuda_bf16.h>

// Sliding-window unfold: out[b, i, j] = x[b, i + j]
//   x:   [B=128, L=8192]  float32
//   out: [B=128, NWIN=8162, W=31] float32
//
// R6r: skewed-smem scalar LDS + 8 outputs/thread, both stores dense:
// thread t writes quads at o0+4t and o0+1024+4t (consecutive lanes write
// consecutive 16B -> fully coalesced STG.128).

static constexpr unsigned Bv    = 128u;
static constexpr unsigned Lv    = 8192u;
static constexpr unsigned Wv    = 31u;
static constexpr unsigned Rv    = Wv / 2u;           // 15
static constexpr unsigned NWIN  = Lv - 2u * Rv;      // 8162
static constexpr unsigned ROW   = NWIN * Wv;         // 253022
static constexpr unsigned TOTAL = Bv * ROW;          // 32,386,816
static constexpr unsigned OUTS_PER_BLOCK = 2048u;    // 256 thr x 8
static constexpr unsigned HALF  = 1024u;
static constexpr unsigned NBLOCKS = (TOTAL + OUTS_PER_BLOCK - 1u) / OUTS_PER_BLOCK; // 15814

static constexpr unsigned SPAN  = 104u;              // staged floats (max src = i0+97)
static constexpr unsigned SPHYS = SPAN + SPAN / 32u + 1u;  // 108

__global__ void __launch_bounds__(256)
WindowAlignmentLayer_65876208386448_kernel(const float* __restrict__ x,
                                           float* __restrict__ out) {
    __shared__ float sx[SPHYS];

    const unsigned t  = threadIdx.x;
    const unsigned o0 = blockIdx.x * OUTS_PER_BLOCK;

    const unsigned b0   = o0 / ROW;                    // magic-multiply
    const unsigned rem0 = o0 - b0 * ROW;

    // Block-uniform predicate (depends only on o0) -> no divergent syncs.
    const bool fast = (rem0 + OUTS_PER_BLOCK <= ROW) && (o0 + OUTS_PER_BLOCK <= TOTAL);

    if (fast) {
        const unsigned i0 = rem0 / Wv;
        const float* __restrict__ xrow = x + (size_t)b0 * Lv;

        // Stage sources [i0, i0+SPAN): phys(idx) = idx + idx/32 (skew).
        if (t < SPAN) {
            unsigned g = i0 + t;
            sx[t + (t >> 5)] = xrow[g < Lv ? g : (Lv - 1u)];
        }
        __syncthreads();

        // --- quad 0: flat outputs o0 + 4t .. +3 ---
        const unsigned rem = rem0 + t * 4u;
        const unsigned i   = rem / Wv;                 // magic-multiply
        const unsigned j   = rem - i * Wv;
        const unsigned sA  = i - i0 + j;
        const unsigned m   = Wv - j;                   // k >= m -> window wrap (-30)

        float4 q0;
        {
            float v[4];
#pragma unroll
            for (unsigned k = 0; k < 4u; ++k) {
                unsigned src = sA + k - ((k >= m) ? (Wv - 1u) : 0u);
                v[k] = sx[src + (src >> 5)];
            }
            q0.x = v[0]; q0.y = v[1]; q0.z = v[2]; q0.w = v[3];
        }

        // --- quad 1: flat outputs o0 + 1024 + 4t (1024 = 33*31 + 1) ---
        unsigned j2   = j + 1u;
        unsigned iadd = 33u;
        if (j2 == Wv) { j2 = 0u; iadd = 34u; }
        const unsigned sA2 = (i + iadd) - i0 + j2;
        const unsigned m2  = Wv - j2;

        float4 q1;
        {
            float v[4];
#pragma unroll
            for (unsigned k = 0; k < 4u; ++k) {
                unsigned src = sA2 + k - ((k >= m2) ? (Wv - 1u) : 0u);
                v[k] = sx[src + (src >> 5)];
            }
            q1.x = v[0]; q1.y = v[1]; q1.z = v[2]; q1.w = v[3];
        }

        *reinterpret_cast<float4*>(out + (o0 + t * 4u))        = q0;
        *reinterpret_cast<float4*>(out + (o0 + HALF + t * 4u)) = q1;
    } else {
        // Cold path: straddles a batch row, or partial tail (~128 blocks).
        for (unsigned k = 0; k < 8u; ++k) {
            unsigned o = o0 + t + k * 256u;            // coalesced scalar stores
            if (o < TOTAL) {
                unsigned b   = o / ROW;
                unsigned rem = o - b * ROW;
                unsigned i   = rem / Wv;
                unsigned j   = rem - i * Wv;
                out[o] = __ldg(x + (size_t)b * Lv + (i + j));
            }
        }
    }
}

extern "C" void kernel_launch(void* const* d_in, const int* in_sizes, int n_in,
                              void* d_out, int out_size) {
    (void)in_sizes; (void)n_in; (void)out_size;
    const float* x   = (const float*)d_in[0];
    float*       out = (float*)d_out;

    WindowAlignmentLayer_65876208386448_kernel<<<NBLOCKS, 256>>>(x, out);
}

// round 8
// speedup vs baseline: 1.5064x; 1.0753x over previous
#include <cuda_runtime.h>
#include <cuda_bf16.h>

// Sliding-window unfold: out[b, i, j] = x[b, i + j]
//   x:   [B=128, L=8192]  float32
//   out: [B=128, NWIN=8162, W=31] float32
//
// R8: R6r structure scaled to 16 outputs/thread. Block = 4096 consecutive
// flat outputs; thread t writes 4 dense quads at o0 + 1024q + 4t (all
// STG.128 fully coalesced). One magic-divide pair per thread; quads 1..3
// derived incrementally (1024 = 33*31 + 1). Loads via skewed smem scalar LDS.

static constexpr unsigned Bv    = 128u;
static constexpr unsigned Lv    = 8192u;
static constexpr unsigned Wv    = 31u;
static constexpr unsigned Rv    = Wv / 2u;           // 15
static constexpr unsigned NWIN  = Lv - 2u * Rv;      // 8162
static constexpr unsigned ROW   = NWIN * Wv;         // 253022
static constexpr unsigned TOTAL = Bv * ROW;          // 32,386,816
static constexpr unsigned OUTS_PER_BLOCK = 4096u;    // 256 thr x 16
static constexpr unsigned QSTEP = 1024u;             // = 33*31 + 1
static constexpr unsigned NBLOCKS = (TOTAL + OUTS_PER_BLOCK - 1u) / OUTS_PER_BLOCK; // 7907

static constexpr unsigned SPAN  = 168u;              // staged floats (max src = i0+162)
static constexpr unsigned SPHYS = SPAN + SPAN / 32u + 1u;  // 174

__global__ void __launch_bounds__(256)
WindowAlignmentLayer_65876208386448_kernel(const float* __restrict__ x,
                                           float* __restrict__ out) {
    __shared__ float sx[SPHYS];

    const unsigned t  = threadIdx.x;
    const unsigned o0 = blockIdx.x * OUTS_PER_BLOCK;

    const unsigned b0   = o0 / ROW;                    // magic-multiply
    const unsigned rem0 = o0 - b0 * ROW;

    // Block-uniform predicate (depends only on o0) -> no divergent syncs.
    const bool fast = (rem0 + OUTS_PER_BLOCK <= ROW) && (o0 + OUTS_PER_BLOCK <= TOTAL);

    if (fast) {
        const unsigned i0 = rem0 / Wv;
        const float* __restrict__ xrow = x + (size_t)b0 * Lv;

        // Stage sources [i0, i0+SPAN): phys(idx) = idx + idx/32 (skew).
        if (t < SPAN) {
            unsigned g = i0 + t;
            sx[t + (t >> 5)] = xrow[g < Lv ? g : (Lv - 1u)];
        }
        __syncthreads();

        // Quad 0 indices via one magic-divide pair; quads 1..3 incremental.
        const unsigned rem = rem0 + t * 4u;
        unsigned iq = rem / Wv;                        // magic-multiply
        unsigned jq = rem - iq * Wv;

        float* __restrict__ ob = out + (o0 + t * 4u);

#pragma unroll
        for (unsigned q = 0; q < 4u; ++q) {
            const unsigned sA = iq + jq - i0;          // local src base (run A)
            const unsigned m  = Wv - jq;               // k >= m -> window wrap (-30)

            float v[4];
#pragma unroll
            for (unsigned k = 0; k < 4u; ++k) {
                unsigned src = sA + k - ((k >= m) ? (Wv - 1u) : 0u);
                v[k] = sx[src + (src >> 5)];
            }
            float4 q4;
            q4.x = v[0]; q4.y = v[1]; q4.z = v[2]; q4.w = v[3];
            *reinterpret_cast<float4*>(ob + q * QSTEP) = q4;

            // advance (i,j) by +1024 flat outputs: i += 33, j += 1 (wrap at 31)
            jq += 1u; iq += 33u;
            if (jq == Wv) { jq = 0u; iq += 1u; }
        }
    } else {
        // Cold path: straddles a batch row, or partial tail (~130 blocks).
        for (unsigned k = 0; k < 16u; ++k) {
            unsigned o = o0 + t + k * 256u;            // coalesced scalar stores
            if (o < TOTAL) {
                unsigned b   = o / ROW;
                unsigned rem = o - b * ROW;
                unsigned i   = rem / Wv;
                unsigned j   = rem - i * Wv;
                out[o] = __ldg(x + (size_t)b * Lv + (i + j));
            }
        }
    }
}

extern "C" void kernel_launch(void* const* d_in, const int* in_sizes, int n_in,
                              void* d_out, int out_size) {
    (void)in_sizes; (void)n_in; (void)out_size;
    const float* x   = (const float*)d_in[0];
    float*       out = (float*)d_out;

    WindowAlignmentLayer_65876208386448_kernel<<<NBLOCKS, 256>>>(x, out);
}

// round 9
// speedup vs baseline: 1.6200x; 1.0754x over previous
#include <cuda_runtime.h>
#include <cuda_bf16.h>

// Sliding-window unfold: out[b, i, j] = x[b, i + j]
//   x:   [B=128, L=8192]  float32
//   out: [B=128, NWIN=8162, W=31] float32
//
// R9: R8 scaled to 32 outputs/thread (8 dense STG.128 quads at o0+1024q+4t),
// streaming stores (__stcs), skewed conflict-free smem scalar LDS.
// One magic-divide pair per thread; quads 1..7 incremental (1024 = 33*31+1).

static constexpr unsigned Bv    = 128u;
static constexpr unsigned Lv    = 8192u;
static constexpr unsigned Wv    = 31u;
static constexpr unsigned Rv    = Wv / 2u;           // 15
static constexpr unsigned NWIN  = Lv - 2u * Rv;      // 8162
static constexpr unsigned ROW   = NWIN * Wv;         // 253022
static constexpr unsigned TOTAL = Bv * ROW;          // 32,386,816
static constexpr unsigned OUTS_PER_BLOCK = 8192u;    // 256 thr x 32
static constexpr unsigned QSTEP = 1024u;             // = 33*31 + 1
static constexpr unsigned NQ    = 8u;                // quads per thread
static constexpr unsigned NBLOCKS = (TOTAL + OUTS_PER_BLOCK - 1u) / OUTS_PER_BLOCK; // 3954

static constexpr unsigned SPAN  = 304u;              // staged floats (src <= i0+296)
static constexpr unsigned SPHYS = SPAN + SPAN / 32u + 1u;  // 314

__global__ void __launch_bounds__(256)
WindowAlignmentLayer_65876208386448_kernel(const float* __restrict__ x,
                                           float* __restrict__ out) {
    __shared__ float sx[SPHYS];

    const unsigned t  = threadIdx.x;
    const unsigned o0 = blockIdx.x * OUTS_PER_BLOCK;

    const unsigned b0   = o0 / ROW;                    // magic-multiply
    const unsigned rem0 = o0 - b0 * ROW;

    // Block-uniform predicate (depends only on o0) -> no divergent syncs.
    const bool fast = (rem0 + OUTS_PER_BLOCK <= ROW) && (o0 + OUTS_PER_BLOCK <= TOTAL);

    if (fast) {
        const unsigned i0 = rem0 / Wv;
        const float* __restrict__ xrow = x + (size_t)b0 * Lv;

        // Stage sources [i0, i0+SPAN): phys(idx) = idx + idx/32 (skew).
#pragma unroll
        for (unsigned c = t; c < SPAN; c += 256u) {
            unsigned g = i0 + c;
            sx[c + (c >> 5)] = xrow[g < Lv ? g : (Lv - 1u)];
        }
        __syncthreads();

        // Quad 0 indices via one magic-divide pair; quads 1..7 incremental.
        const unsigned rem = rem0 + t * 4u;
        unsigned iq = rem / Wv;                        // magic-multiply
        unsigned jq = rem - iq * Wv;

        float* __restrict__ ob = out + (o0 + t * 4u);

#pragma unroll
        for (unsigned q = 0; q < NQ; ++q) {
            const unsigned sA = iq + jq - i0;          // local src base (run A)
            const unsigned m  = Wv - jq;               // k >= m -> window wrap (-30)

            float v[4];
#pragma unroll
            for (unsigned k = 0; k < 4u; ++k) {
                unsigned src = sA + k - ((k >= m) ? (Wv - 1u) : 0u);
                v[k] = sx[src + (src >> 5)];
            }
            float4 q4;
            q4.x = v[0]; q4.y = v[1]; q4.z = v[2]; q4.w = v[3];
            __stcs(reinterpret_cast<float4*>(ob + q * QSTEP), q4);

            // advance (i,j) by +1024 flat outputs: i += 33, j += 1 (wrap at 31)
            jq += 1u; iq += 33u;
            if (jq == Wv) { jq = 0u; iq += 1u; }
        }
    } else {
        // Cold path: straddles a batch row, or partial tail (~130 blocks).
        for (unsigned k = 0; k < 32u; ++k) {
            unsigned o = o0 + t + k * 256u;            // coalesced scalar stores
            if (o < TOTAL) {
                unsigned b   = o / ROW;
                unsigned rem = o - b * ROW;
                unsigned i   = rem / Wv;
                unsigned j   = rem - i * Wv;
                out[o] = __ldg(x + (size_t)b * Lv + (i + j));
            }
        }
    }
}

extern "C" void kernel_launch(void* const* d_in, const int* in_sizes, int n_in,
                              void* d_out, int out_size) {
    (void)in_sizes; (void)n_in; (void)out_size;
    const float* x   = (const float*)d_in[0];
    float*       out = (float*)d_out;

    WindowAlignmentLayer_65876208386448_kernel<<<NBLOCKS, 256>>>(x, out);
}